// round 1
// baseline (speedup 1.0000x reference)
#include <cuda_runtime.h>
#include <math.h>

#define NT 256

// All per-sample state + all small weights live in dynamic shared memory.
struct SmemLayout {
    float xs[3 * 34 * 34];    // padded input (3468) ; reused as tmp[2592] in the loop
    float p1p[8 * 17 * 17];   // padded pool1 output (2312)
    float p2[16 * 7 * 7];     // pool2 output (784)
    float f[32 * 81];         // feature map (2592)
    float q[16 * 81];         // q conv output (1296)
    float w1[8 * 3 * 25];  float b1[8];
    float w2[16 * 8 * 9];  float b2[16];
    float w3[32 * 16];     float b3[32];
    float wcf_t[32 * 64];  float bcf[64];   // conf conv weights, transposed [ic][oc]
    float wcfc[1024];      float bcfc[1];
    float wq[16 * 32];     float bq[16];
    float wa[32 * 48];     float ba[32];
    float red[40];                         // conf reduction + flag
    float clsred[(NT / 32) * 10];          // classifier partials
};

__global__ __launch_bounds__(NT)
void TM_20005957665089_kernel(
    const float* __restrict__ gx,
    const float* __restrict__ gw1,  const float* __restrict__ gb1,
    const float* __restrict__ gw2,  const float* __restrict__ gb2,
    const float* __restrict__ gw3,  const float* __restrict__ gb3,
    const float* __restrict__ gwcf, const float* __restrict__ gbcf,
    const float* __restrict__ gwcfc,const float* __restrict__ gbcfc,
    const float* __restrict__ gwq,  const float* __restrict__ gbq,
    const float* __restrict__ gwa,  const float* __restrict__ gba,
    const float* __restrict__ gwcls,const float* __restrict__ gbcls,
    float* __restrict__ gout)
{
    extern __shared__ float smem_raw[];
    SmemLayout* s = reinterpret_cast<SmemLayout*>(smem_raw);
    const int tid = threadIdx.x;
    const int b   = blockIdx.x;

    // ---- Phase 0: zero padded buffers, load weights ----
    for (int i = tid; i < 3468; i += NT) s->xs[i]  = 0.f;
    for (int i = tid; i < 2312; i += NT) s->p1p[i] = 0.f;
    for (int i = tid; i < 600;  i += NT) s->w1[i] = gw1[i];
    for (int i = tid; i < 8;    i += NT) s->b1[i] = gb1[i];
    for (int i = tid; i < 1152; i += NT) s->w2[i] = gw2[i];
    for (int i = tid; i < 16;   i += NT) s->b2[i] = gb2[i];
    for (int i = tid; i < 512;  i += NT) s->w3[i] = gw3[i];
    for (int i = tid; i < 32;   i += NT) s->b3[i] = gb3[i];
    for (int i = tid; i < 2048; i += NT) {          // transpose w_cf to [ic][oc]
        int oc = i >> 5, ic = i & 31;
        s->wcf_t[ic * 64 + oc] = gwcf[i];
    }
    for (int i = tid; i < 64;   i += NT) s->bcf[i]  = gbcf[i];
    for (int i = tid; i < 1024; i += NT) s->wcfc[i] = gwcfc[i];
    if (tid == 0) s->bcfc[0] = gbcfc[0];
    for (int i = tid; i < 512;  i += NT) s->wq[i] = gwq[i];
    for (int i = tid; i < 16;   i += NT) s->bq[i] = gbq[i];
    for (int i = tid; i < 1536; i += NT) s->wa[i] = gwa[i];
    for (int i = tid; i < 32;   i += NT) s->ba[i] = gba[i];
    __syncthreads();

    // ---- Phase 1: load x into padded smem (pad 1 for the 5x5 conv) ----
    const float* xin = gx + (size_t)b * 3072;
    for (int i = tid; i < 3072; i += NT) {
        int c = i >> 10, r = (i >> 5) & 31, cc = i & 31;
        s->xs[c * 1156 + (r + 1) * 34 + (cc + 1)] = xin[i];
    }
    __syncthreads();

    // ---- Phase 2: conv1 (3->8, 5x5, pad1) + relu + maxpool2 -> p1p interior ----
    // conv out 30x30, pooled 15x15, written at +1 border offset (pad for conv2)
    for (int idx = tid; idx < 1800; idx += NT) {
        int c  = idx / 225;
        int r  = idx % 225;
        int py = r / 15, px = r % 15;
        int y0 = 2 * py, x0 = 2 * px;
        const float* wp = &s->w1[c * 75];
        float m = -3.4e38f;
        #pragma unroll
        for (int dy = 0; dy < 2; dy++)
        #pragma unroll
        for (int dx = 0; dx < 2; dx++) {
            float acc = s->b1[c];
            #pragma unroll
            for (int ic = 0; ic < 3; ic++) {
                const float* xp = &s->xs[ic * 1156 + (y0 + dy) * 34 + (x0 + dx)];
                #pragma unroll
                for (int ky = 0; ky < 5; ky++)
                #pragma unroll
                for (int kx = 0; kx < 5; kx++)
                    acc += xp[ky * 34 + kx] * wp[ic * 25 + ky * 5 + kx];
            }
            m = fmaxf(m, acc);
        }
        s->p1p[c * 289 + (py + 1) * 17 + (px + 1)] = fmaxf(m, 0.f);
    }
    __syncthreads();

    // ---- Phase 3: conv2 (8->16, 3x3, pad1) + relu + maxpool2 (15->7) -> p2 ----
    for (int idx = tid; idx < 784; idx += NT) {
        int c  = idx / 49;
        int r  = idx % 49;
        int py = r / 7, px = r % 7;
        const float* wp = &s->w2[c * 72];
        float m = -3.4e38f;
        #pragma unroll
        for (int dy = 0; dy < 2; dy++)
        #pragma unroll
        for (int dx = 0; dx < 2; dx++) {
            float acc = s->b2[c];
            #pragma unroll
            for (int ic = 0; ic < 8; ic++) {
                const float* pp = &s->p1p[ic * 289 + (2 * py + dy) * 17 + (2 * px + dx)];
                #pragma unroll
                for (int ky = 0; ky < 3; ky++)
                #pragma unroll
                for (int kx = 0; kx < 3; kx++)
                    acc += pp[ky * 17 + kx] * wp[ic * 9 + ky * 3 + kx];
            }
            m = fmaxf(m, acc);
        }
        s->p2[c * 49 + py * 7 + px] = fmaxf(m, 0.f);
    }
    __syncthreads();

    // ---- Phase 4: conv3 (16->32, 1x1, pad1!) -> f [32,9,9]; border = bias ----
    for (int idx = tid; idx < 2592; idx += NT) {
        int oc = idx / 81;
        int r  = idx % 81;
        int y  = r / 9, x = r % 9;
        float v = s->b3[oc];
        if ((unsigned)(y - 1) < 7u && (unsigned)(x - 1) < 7u) {
            const float* pp = &s->p2[(y - 1) * 7 + (x - 1)];
            const float* wp = &s->w3[oc * 16];
            #pragma unroll
            for (int ic = 0; ic < 16; ic++) v += wp[ic] * pp[ic * 49];
        }
        s->f[idx] = v;
    }
    __syncthreads();

    // ---- Phase 5: adaptive depth loop ----
    for (int depth = 0; depth < 8; depth++) {
        // --- confidence head: relu(conv_cf(f)) -> pool(9->4) -> dot w_cfc ---
        // thread: fixed oc = tid&63, fixed px = tid>>6 (0..3), covers y=0..7, x={2px,2px+1}
        {
            const int c  = tid & 63;
            const int px = tid >> 6;
            const int xb = 2 * px;
            float acc[8][2];
            const float bc = s->bcf[c];
            #pragma unroll
            for (int y = 0; y < 8; y++) { acc[y][0] = bc; acc[y][1] = bc; }
            #pragma unroll 4
            for (int ic = 0; ic < 32; ic++) {
                float wv = s->wcf_t[ic * 64 + c];
                const float* fr = &s->f[ic * 81 + xb];
                #pragma unroll
                for (int y = 0; y < 8; y++) {
                    acc[y][0] += fr[y * 9]     * wv;
                    acc[y][1] += fr[y * 9 + 1] * wv;
                }
            }
            float partial = 0.f;
            #pragma unroll
            for (int py = 0; py < 4; py++) {
                float m = fmaxf(fmaxf(acc[2 * py][0],     acc[2 * py][1]),
                                fmaxf(acc[2 * py + 1][0], acc[2 * py + 1][1]));
                m = fmaxf(m, 0.f);
                partial += m * s->wcfc[c * 16 + py * 4 + px];
            }
            #pragma unroll
            for (int o = 16; o > 0; o >>= 1)
                partial += __shfl_down_sync(0xffffffffu, partial, o);
            if ((tid & 31) == 0) s->red[tid >> 5] = partial;
        }
        __syncthreads();
        if (tid == 0) {
            float logit = s->bcfc[0];
            #pragma unroll
            for (int w = 0; w < NT / 32; w++) logit += s->red[w];
            float confv = 1.f / (1.f + expf(-logit));
            s->red[32] = (confv < 0.9f) ? 1.f : 0.f;   // active?
        }
        __syncthreads();
        if (s->red[32] == 0.f) break;   // sample frozen: f never changes again

        // --- q = conv_q(f) : 32 -> 16 channels, 1x1 ---
        for (int idx = tid; idx < 1296; idx += NT) {
            int oc = idx / 81, pos = idx % 81;
            float a = s->bq[oc];
            const float* wp = &s->wq[oc * 32];
            const float* fp = &s->f[pos];
            #pragma unroll
            for (int ic = 0; ic < 32; ic++) a += wp[ic] * fp[ic * 81];
            s->q[idx] = a;
        }
        __syncthreads();

        // --- a = tanh(conv_a(concat[q, f])) : 48 -> 32 channels, 1x1 ---
        float* tmp = s->xs;   // xs no longer needed
        for (int idx = tid; idx < 2592; idx += NT) {
            int oc = idx / 81, pos = idx % 81;
            float a = s->ba[oc];
            const float* wp = &s->wa[oc * 48];
            const float* qp = &s->q[pos];
            const float* fp = &s->f[pos];
            #pragma unroll
            for (int j = 0; j < 16; j++) a += wp[j]      * qp[j * 81];
            #pragma unroll
            for (int j = 0; j < 32; j++) a += wp[16 + j] * fp[j * 81];
            tmp[idx] = tanhf(a);
        }
        __syncthreads();
        for (int idx = tid; idx < 2592; idx += NT) s->f[idx] += tmp[idx];
        __syncthreads();
    }

    // ---- Phase 6: classifier out[10] = w_cls @ f_flat + b_cls ----
    {
        float ac[10];
        #pragma unroll
        for (int o = 0; o < 10; o++) ac[o] = 0.f;
        for (int i = tid; i < 2592; i += NT) {
            float fv = s->f[i];
            #pragma unroll
            for (int o = 0; o < 10; o++)
                ac[o] += __ldg(&gwcls[o * 2592 + i]) * fv;
        }
        #pragma unroll
        for (int o = 0; o < 10; o++) {
            float v = ac[o];
            #pragma unroll
            for (int sh = 16; sh > 0; sh >>= 1)
                v += __shfl_down_sync(0xffffffffu, v, sh);
            if ((tid & 31) == 0) s->clsred[(tid >> 5) * 10 + o] = v;
        }
        __syncthreads();
        if (tid < 10) {
            float v = gbcls[tid];
            #pragma unroll
            for (int w = 0; w < NT / 32; w++) v += s->clsred[w * 10 + tid];
            gout[(size_t)b * 10 + tid] = v;
        }
    }
}

extern "C" void kernel_launch(void* const* d_in, const int* in_sizes, int n_in,
                              void* d_out, int out_size) {
    const float* x     = (const float*)d_in[0];
    const float* w_b1  = (const float*)d_in[1];
    const float* b_b1  = (const float*)d_in[2];
    const float* w_b2  = (const float*)d_in[3];
    const float* b_b2  = (const float*)d_in[4];
    const float* w_b3  = (const float*)d_in[5];
    const float* b_b3  = (const float*)d_in[6];
    const float* w_cf  = (const float*)d_in[7];
    const float* b_cf  = (const float*)d_in[8];
    const float* w_cfc = (const float*)d_in[9];
    const float* b_cfc = (const float*)d_in[10];
    const float* w_q   = (const float*)d_in[11];
    const float* b_q   = (const float*)d_in[12];
    const float* w_a   = (const float*)d_in[13];
    const float* b_a   = (const float*)d_in[14];
    const float* w_cls = (const float*)d_in[15];
    const float* b_cls = (const float*)d_in[16];
    float* out = (float*)d_out;

    int B = in_sizes[0] / (3 * 32 * 32);
    size_t smem = sizeof(SmemLayout);
    cudaFuncSetAttribute(TM_20005957665089_kernel,
                         cudaFuncAttributeMaxDynamicSharedMemorySize, (int)smem);
    TM_20005957665089_kernel<<<B, NT, smem>>>(
        x, w_b1, b_b1, w_b2, b_b2, w_b3, b_b3,
        w_cf, b_cf, w_cfc, b_cfc, w_q, b_q, w_a, b_a,
        w_cls, b_cls, out);
}

// round 2
// speedup vs baseline: 2.1593x; 2.1593x over previous
#include <cuda_runtime.h>
#include <math.h>

#define NT 256

struct SmemLayout {
    float xs[3 * 34 * 34];    // padded input (3468)
    float p1p[8 * 17 * 17];   // padded pool1 output (2312)
    float p2[16 * 7 * 7];     // pool2 output (784)
    float f[32 * 81];         // feature map (2592)
    float w1[8 * 3 * 25];  float b1[8];
    float w2[16 * 8 * 9];  float b2[16];
    float w3[32 * 16];     float b3[32];
    float wcf_t[32 * 64];  float bcf[64];   // conf conv weights, transposed [ic][oc]
    float wcfc[1024];      float bcfc[1];
    float weff_t[32 * 32]; float beff[32];  // fused (a ∘ q) weights, [ic][oc]
    float red[40];                          // conf reduction + active flag
    float clsred[(NT / 32) * 10];
};

__device__ __forceinline__ float fast_tanh(float x) {
    // tanh(x) = 1 - 2/(exp(2x)+1); exp via ex2.approx, div via rcp.approx.
    float t, r;
    asm("ex2.approx.f32 %0, %1;" : "=f"(t) : "f"(x * 2.885390082f)); // 2*log2(e)
    asm("rcp.approx.f32 %0, %1;" : "=f"(r) : "f"(t + 1.0f));
    return 1.0f - 2.0f * r;
}

__global__ __launch_bounds__(NT)
void TM_20005957665089_kernel(
    const float* __restrict__ gx,
    const float* __restrict__ gw1,  const float* __restrict__ gb1,
    const float* __restrict__ gw2,  const float* __restrict__ gb2,
    const float* __restrict__ gw3,  const float* __restrict__ gb3,
    const float* __restrict__ gwcf, const float* __restrict__ gbcf,
    const float* __restrict__ gwcfc,const float* __restrict__ gbcfc,
    const float* __restrict__ gwq,  const float* __restrict__ gbq,
    const float* __restrict__ gwa,  const float* __restrict__ gba,
    const float* __restrict__ gwcls,const float* __restrict__ gbcls,
    float* __restrict__ gout)
{
    extern __shared__ float smem_raw[];
    SmemLayout* s = reinterpret_cast<SmemLayout*>(smem_raw);
    const int tid  = threadIdx.x;
    const int lane = tid & 31;
    const int b    = blockIdx.x;

    // ---- Phase 0: zero padded buffers, load/precompute weights ----
    for (int i = tid; i < 3468; i += NT) s->xs[i]  = 0.f;
    for (int i = tid; i < 2312; i += NT) s->p1p[i] = 0.f;
    for (int i = tid; i < 600;  i += NT) s->w1[i] = gw1[i];
    for (int i = tid; i < 8;    i += NT) s->b1[i] = gb1[i];
    for (int i = tid; i < 1152; i += NT) s->w2[i] = gw2[i];
    for (int i = tid; i < 16;   i += NT) s->b2[i] = gb2[i];
    for (int i = tid; i < 512;  i += NT) s->w3[i] = gw3[i];
    for (int i = tid; i < 32;   i += NT) s->b3[i] = gb3[i];
    for (int i = tid; i < 2048; i += NT) {          // transpose w_cf to [ic][oc]
        int oc = i >> 5, ic = i & 31;
        s->wcf_t[ic * 64 + oc] = gwcf[i];
    }
    for (int i = tid; i < 64;   i += NT) s->bcf[i]  = gbcf[i];
    for (int i = tid; i < 1024; i += NT) s->wcfc[i] = gwcfc[i];
    if (tid == 0) s->bcfc[0] = gbcfc[0];
    // W_eff[oc][ic] = w_a[oc][16+ic] + sum_j w_a[oc][j] * w_q[j][ic]   (j<16)
    for (int o = tid; o < 1024; o += NT) {
        int oc = o >> 5, ic = o & 31;
        float v = __ldg(&gwa[oc * 48 + 16 + ic]);
        #pragma unroll
        for (int j = 0; j < 16; j++)
            v += __ldg(&gwa[oc * 48 + j]) * __ldg(&gwq[j * 32 + ic]);
        s->weff_t[ic * 32 + oc] = v;
    }
    if (tid < 32) {
        float v = __ldg(&gba[tid]);
        #pragma unroll
        for (int j = 0; j < 16; j++)
            v += __ldg(&gwa[tid * 48 + j]) * __ldg(&gbq[j]);
        s->beff[tid] = v;
    }
    __syncthreads();

    // ---- Phase 1: load x into padded smem (pad 1 for the 5x5 conv) ----
    const float* xin = gx + (size_t)b * 3072;
    for (int i = tid; i < 3072; i += NT) {
        int c = i >> 10, r = (i >> 5) & 31, cc = i & 31;
        s->xs[c * 1156 + (r + 1) * 34 + (cc + 1)] = xin[i];
    }
    __syncthreads();

    // ---- Phase 2: conv1 (3->8, 5x5, pad1) + relu + maxpool2 -> p1p interior ----
    for (int idx = tid; idx < 1800; idx += NT) {
        int c  = idx / 225;
        int r  = idx % 225;
        int py = r / 15, px = r % 15;
        const float* wp = &s->w1[c * 75];
        float bias = s->b1[c];
        float acc[2][2] = {{bias, bias}, {bias, bias}};
        #pragma unroll
        for (int ic = 0; ic < 3; ic++) {
            const float* xb = &s->xs[ic * 1156 + 2 * py * 34 + 2 * px];
            #pragma unroll
            for (int ky = 0; ky < 5; ky++)
            #pragma unroll
            for (int kx = 0; kx < 5; kx++) {
                float wv = wp[ic * 25 + ky * 5 + kx];
                const float* xp = &xb[ky * 34 + kx];
                acc[0][0] += xp[0]  * wv;
                acc[0][1] += xp[1]  * wv;
                acc[1][0] += xp[34] * wv;
                acc[1][1] += xp[35] * wv;
            }
        }
        float m = fmaxf(fmaxf(acc[0][0], acc[0][1]), fmaxf(acc[1][0], acc[1][1]));
        s->p1p[c * 289 + (py + 1) * 17 + (px + 1)] = fmaxf(m, 0.f);
    }
    __syncthreads();

    // ---- Phase 3: conv2 (8->16, 3x3, pad1) + relu + maxpool2 (15->7) -> p2 ----
    for (int idx = tid; idx < 784; idx += NT) {
        int c  = idx / 49;
        int r  = idx % 49;
        int py = r / 7, px = r % 7;
        const float* wp = &s->w2[c * 72];
        float bias = s->b2[c];
        float acc[2][2] = {{bias, bias}, {bias, bias}};
        #pragma unroll
        for (int ic = 0; ic < 8; ic++) {
            const float* pb = &s->p1p[ic * 289 + 2 * py * 17 + 2 * px];
            #pragma unroll
            for (int ky = 0; ky < 3; ky++)
            #pragma unroll
            for (int kx = 0; kx < 3; kx++) {
                float wv = wp[ic * 9 + ky * 3 + kx];
                const float* pp = &pb[ky * 17 + kx];
                acc[0][0] += pp[0]  * wv;
                acc[0][1] += pp[1]  * wv;
                acc[1][0] += pp[17] * wv;
                acc[1][1] += pp[18] * wv;
            }
        }
        float m = fmaxf(fmaxf(acc[0][0], acc[0][1]), fmaxf(acc[1][0], acc[1][1]));
        s->p2[c * 49 + py * 7 + px] = fmaxf(m, 0.f);
    }
    __syncthreads();

    // ---- Phase 4: conv3 (16->32, 1x1, pad1!) -> f [32,9,9]; border = bias ----
    for (int idx = tid; idx < 2592; idx += NT) {
        int oc = idx / 81;
        int r  = idx % 81;
        int y  = r / 9, x = r % 9;
        float v = s->b3[oc];
        if ((unsigned)(y - 1) < 7u && (unsigned)(x - 1) < 7u) {
            const float* pp = &s->p2[(y - 1) * 7 + (x - 1)];
            const float* wp = &s->w3[oc * 16];
            #pragma unroll
            for (int ic = 0; ic < 16; ic++) v += wp[ic] * pp[ic * 49];
        }
        s->f[idx] = v;
    }
    __syncthreads();

    // Thread roles in the depth loop:
    const int ocg  = tid >> 5;         // conf: warp = 8-oc group | a-conv: 4-oc group
    const int px4  = lane & 3;         // conf: pooled x (0..3)
    const int yr   = lane >> 2;        // conf: conv row (0..7)
    const int pg   = lane;             // a-conv: 3-pos group, active if < 27

    // ---- Phase 5: adaptive depth loop ----
    for (int depth = 0; depth < 8; depth++) {
        // --- confidence head: relu(conv_cf(f)) -> pool(9->4) -> dot w_cfc ---
        {
            float acc[8][2];
            #pragma unroll
            for (int k = 0; k < 8; k++) {
                float bv = s->bcf[ocg * 8 + k];
                acc[k][0] = bv; acc[k][1] = bv;
            }
            const int fo = yr * 9 + 2 * px4;
            #pragma unroll 4
            for (int ic = 0; ic < 32; ic++) {
                float f0 = s->f[ic * 81 + fo];
                float f1 = s->f[ic * 81 + fo + 1];
                const float* wr = &s->wcf_t[ic * 64 + ocg * 8];
                #pragma unroll
                for (int k = 0; k < 8; k++) {
                    float wv = wr[k];
                    acc[k][0] += f0 * wv;
                    acc[k][1] += f1 * wv;
                }
            }
            float partial = 0.f;
            #pragma unroll
            for (int k = 0; k < 8; k++) {
                float m = fmaxf(acc[k][0], acc[k][1]);
                m = fmaxf(m, __shfl_xor_sync(0xffffffffu, m, 4));
                m = fmaxf(m, 0.f);
                if ((yr & 1) == 0)
                    partial += m * s->wcfc[(ocg * 8 + k) * 16 + (yr >> 1) * 4 + px4];
            }
            #pragma unroll
            for (int o = 16; o > 0; o >>= 1)
                partial += __shfl_down_sync(0xffffffffu, partial, o);
            if (lane == 0) s->red[ocg] = partial;
        }
        __syncthreads();
        if (tid == 0) {
            float logit = s->bcfc[0];
            #pragma unroll
            for (int w = 0; w < 8; w++) logit += s->red[w];
            float confv = 1.f / (1.f + expf(-logit));
            s->red[32] = (confv < 0.9f) ? 1.f : 0.f;
        }
        __syncthreads();
        if (s->red[32] == 0.f) break;   // frozen: f never changes again

        // --- fused residual: f += tanh(W_eff @ f + b_eff)  (32x81, K=32) ---
        float acc[4][3];
        if (pg < 27) {
            #pragma unroll
            for (int k = 0; k < 4; k++) {
                float bv = s->beff[ocg * 4 + k];
                acc[k][0] = bv; acc[k][1] = bv; acc[k][2] = bv;
            }
            const int po = pg * 3;
            #pragma unroll 4
            for (int ic = 0; ic < 32; ic++) {
                float f0 = s->f[ic * 81 + po];
                float f1 = s->f[ic * 81 + po + 1];
                float f2 = s->f[ic * 81 + po + 2];
                const float* wr = &s->weff_t[ic * 32 + ocg * 4];
                #pragma unroll
                for (int k = 0; k < 4; k++) {
                    float wv = wr[k];
                    acc[k][0] += f0 * wv;
                    acc[k][1] += f1 * wv;
                    acc[k][2] += f2 * wv;
                }
            }
        }
        __syncthreads();   // all reads of f complete before writes
        if (pg < 27) {
            #pragma unroll
            for (int k = 0; k < 4; k++) {
                float* fp = &s->f[(ocg * 4 + k) * 81 + pg * 3];
                fp[0] += fast_tanh(acc[k][0]);
                fp[1] += fast_tanh(acc[k][1]);
                fp[2] += fast_tanh(acc[k][2]);
            }
        }
        __syncthreads();
    }

    // ---- Phase 6: classifier out[10] = w_cls @ f_flat + b_cls ----
    {
        float ac[10];
        #pragma unroll
        for (int o = 0; o < 10; o++) ac[o] = 0.f;
        for (int i = tid; i < 2592; i += NT) {
            float fv = s->f[i];
            #pragma unroll
            for (int o = 0; o < 10; o++)
                ac[o] += __ldg(&gwcls[o * 2592 + i]) * fv;
        }
        #pragma unroll
        for (int o = 0; o < 10; o++) {
            float v = ac[o];
            #pragma unroll
            for (int sh = 16; sh > 0; sh >>= 1)
                v += __shfl_down_sync(0xffffffffu, v, sh);
            if (lane == 0) s->clsred[(tid >> 5) * 10 + o] = v;
        }
        __syncthreads();
        if (tid < 10) {
            float v = gbcls[tid];
            #pragma unroll
            for (int w = 0; w < NT / 32; w++) v += s->clsred[w * 10 + tid];
            gout[(size_t)b * 10 + tid] = v;
        }
    }
}

extern "C" void kernel_launch(void* const* d_in, const int* in_sizes, int n_in,
                              void* d_out, int out_size) {
    const float* x     = (const float*)d_in[0];
    const float* w_b1  = (const float*)d_in[1];
    const float* b_b1  = (const float*)d_in[2];
    const float* w_b2  = (const float*)d_in[3];
    const float* b_b2  = (const float*)d_in[4];
    const float* w_b3  = (const float*)d_in[5];
    const float* b_b3  = (const float*)d_in[6];
    const float* w_cf  = (const float*)d_in[7];
    const float* b_cf  = (const float*)d_in[8];
    const float* w_cfc = (const float*)d_in[9];
    const float* b_cfc = (const float*)d_in[10];
    const float* w_q   = (const float*)d_in[11];
    const float* b_q   = (const float*)d_in[12];
    const float* w_a   = (const float*)d_in[13];
    const float* b_a   = (const float*)d_in[14];
    const float* w_cls = (const float*)d_in[15];
    const float* b_cls = (const float*)d_in[16];
    float* out = (float*)d_out;

    int B = in_sizes[0] / (3 * 32 * 32);
    size_t smem = sizeof(SmemLayout);
    cudaFuncSetAttribute(TM_20005957665089_kernel,
                         cudaFuncAttributeMaxDynamicSharedMemorySize, (int)smem);
    TM_20005957665089_kernel<<<B, NT, smem>>>(
        x, w_b1, b_b1, w_b2, b_b2, w_b3, b_b3,
        w_cf, b_cf, w_cfc, b_cfc, w_q, b_q, w_a, b_a,
        w_cls, b_cls, out);
}

// round 3
// speedup vs baseline: 2.1724x; 1.0061x over previous
#include <cuda_runtime.h>
#include <math.h>

#define NT 256
typedef unsigned long long u64;

// ---- f32x2 packed helpers (FFMA2 only reachable via PTX) ----
__device__ __forceinline__ u64 pk2(float lo, float hi) {
    u64 r; asm("mov.b64 %0,{%1,%2};" : "=l"(r) : "f"(lo), "f"(hi)); return r;
}
__device__ __forceinline__ void upk2(u64 v, float& lo, float& hi) {
    asm("mov.b64 {%0,%1},%2;" : "=f"(lo), "=f"(hi) : "l"(v));
}
__device__ __forceinline__ void fma2(u64& d, u64 a, u64 b) {
    asm("fma.rn.f32x2 %0,%1,%2,%0;" : "+l"(d) : "l"(a), "l"(b));
}
__device__ __forceinline__ float fast_tanh(float x) {
    float t, r;
    asm("ex2.approx.f32 %0, %1;" : "=f"(t) : "f"(x * 2.885390082f));
    asm("rcp.approx.f32 %0, %1;" : "=f"(r) : "f"(t + 1.0f));
    return 1.0f - 2.0f * r;
}

struct __align__(16) Smem {
    union {
        float  xs[3 * 34 * 34];          // 3468 fl  (phases 1-2)
        float2 wcf2[32 * 64];            // 16384 B  (depth loop) [ic][oc] dup
    } A;
    union {
        float p1p[8 * 17 * 17];          // 2312 fl  (phases 2-3)
        struct { float2 weff2[32 * 32]; float beff[32]; } L;   // depth loop
    } B;
    union {
        float p2[16 * 49];               // phases 3-4
        struct { float red[40]; float clsred[80]; } R;         // loop + classifier
    } C;
    float  f[32 * 9 * 12];               // padded feature map, rows of 12 (cols 9-11 pad)
    float2 w1d[600];                     // [ic][ky][kx][oc8]  dup pairs
    float2 w2d[1152];                    // [ic][ky][kx][oc16] dup pairs
    float  w3[512];
    float  wcfc[1024];
    float2 bcf2[64];
    float  b1[8], b2[16], b3[32];
    float  bcfc;
};

__global__ __launch_bounds__(NT, 3)
void TM_20005957665089_kernel(
    const float* __restrict__ gx,
    const float* __restrict__ gw1,  const float* __restrict__ gb1,
    const float* __restrict__ gw2,  const float* __restrict__ gb2,
    const float* __restrict__ gw3,  const float* __restrict__ gb3,
    const float* __restrict__ gwcf, const float* __restrict__ gbcf,
    const float* __restrict__ gwcfc,const float* __restrict__ gbcfc,
    const float* __restrict__ gwq,  const float* __restrict__ gbq,
    const float* __restrict__ gwa,  const float* __restrict__ gba,
    const float* __restrict__ gwcls,const float* __restrict__ gbcls,
    float* __restrict__ gout)
{
    extern __shared__ float smem_raw[];
    Smem* s = reinterpret_cast<Smem*>(smem_raw);
    const int tid  = threadIdx.x;
    const int lane = tid & 31;
    const int wid  = tid >> 5;
    const int b    = blockIdx.x;

    // ---- Phase 0: base weights + zero pads ----
    for (int i = tid; i < 3468; i += NT) s->A.xs[i]  = 0.f;
    for (int i = tid; i < 2312; i += NT) s->B.p1p[i] = 0.f;
    for (int i = tid; i < 600; i += NT) {            // w1: [oc][ic][ky][kx] -> [tap][oc] dup
        int oc = i / 75, r = i % 75;
        float v = gw1[i];
        s->w1d[r * 8 + oc] = make_float2(v, v);
    }
    for (int i = tid; i < 1152; i += NT) {           // w2: [oc][ic][ky][kx] -> [tap][oc] dup
        int oc = i / 72, r = i % 72;
        float v = gw2[i];
        s->w2d[r * 16 + oc] = make_float2(v, v);
    }
    for (int i = tid; i < 512;  i += NT) s->w3[i]   = gw3[i];
    for (int i = tid; i < 1024; i += NT) s->wcfc[i] = gwcfc[i];
    for (int i = tid; i < 64;   i += NT) { float v = gbcf[i]; s->bcf2[i] = make_float2(v, v); }
    if (tid < 8)  s->b1[tid] = gb1[tid];
    if (tid < 16) s->b2[tid] = gb2[tid];
    if (tid < 32) s->b3[tid] = gb3[tid];
    if (tid == 0) s->bcfc = gbcfc[0];
    __syncthreads();

    // ---- Phase 1: x into padded smem (pad 1) ----
    const float* xin = gx + (size_t)b * 3072;
    for (int i = tid; i < 3072; i += NT) {
        int c = i >> 10, r = (i >> 5) & 31, cc = i & 31;
        s->A.xs[c * 1156 + (r + 1) * 34 + (cc + 1)] = xin[i];
    }
    __syncthreads();

    // ---- Phase 2: conv1 (3->8, 5x5) + relu + maxpool2 ----
    // thread = one pooled position, ALL 8 oc; acc pairs over conv cols (x0,x0+1)
    if (tid < 225) {
        const int py = tid / 15, px = tid % 15;
        const int x0 = 2 * px, y0 = 2 * py;
        u64 acc[8][2];
        #pragma unroll
        for (int k = 0; k < 8; k++) { acc[k][0] = 0ull; acc[k][1] = 0ull; }
        #pragma unroll
        for (int ic = 0; ic < 3; ic++) {
            const float* xb = &s->A.xs[ic * 1156 + y0 * 34 + x0];
            #pragma unroll
            for (int ky = 0; ky < 5; ky++) {
                const float* pa = xb + ky * 34;
                const float* pb = pa + 34;
                u64 pa2[5], pb2[5];
                #pragma unroll
                for (int kx = 0; kx < 5; kx++) {
                    pa2[kx] = pk2(pa[kx], pa[kx + 1]);
                    pb2[kx] = pk2(pb[kx], pb[kx + 1]);
                }
                const ulonglong2* wp =
                    (const ulonglong2*)&s->w1d[(ic * 25 + ky * 5) * 8];
                #pragma unroll
                for (int kx = 0; kx < 5; kx++) {
                    #pragma unroll
                    for (int j = 0; j < 4; j++) {
                        ulonglong2 w2 = wp[kx * 4 + j];
                        fma2(acc[2*j  ][0], w2.x, pa2[kx]);
                        fma2(acc[2*j  ][1], w2.x, pb2[kx]);
                        fma2(acc[2*j+1][0], w2.y, pa2[kx]);
                        fma2(acc[2*j+1][1], w2.y, pb2[kx]);
                    }
                }
            }
        }
        #pragma unroll
        for (int k = 0; k < 8; k++) {
            float a0, a1, c0, c1;
            upk2(acc[k][0], a0, a1); upk2(acc[k][1], c0, c1);
            float m = fmaxf(fmaxf(a0, a1), fmaxf(c0, c1)) + s->b1[k];
            s->B.p1p[k * 289 + (py + 1) * 17 + (px + 1)] = fmaxf(m, 0.f);
        }
    }
    __syncthreads();

    // ---- Phase 2.5 (xs dead): wcf2 dup-fill   +   Phase 3: conv2 ----
    for (int i = tid; i < 2048; i += NT) {
        int oc = i >> 5, ic = i & 31;
        float v = gwcf[i];
        s->A.wcf2[ic * 64 + oc] = make_float2(v, v);
    }
    // conv2 (8->16, 3x3) + relu + maxpool2: thread = 4 oc x 1 pooled pos
    if (tid < 196) {
        const int ocg = tid / 49;
        const int pos = tid % 49;
        const int py = pos / 7, px = pos % 7;
        u64 acc[4][2];
        #pragma unroll
        for (int k = 0; k < 4; k++) { acc[k][0] = 0ull; acc[k][1] = 0ull; }
        #pragma unroll
        for (int ic = 0; ic < 8; ic++) {
            const float* pbase = &s->B.p1p[ic * 289 + 2 * py * 17 + 2 * px];
            #pragma unroll
            for (int ky = 0; ky < 3; ky++) {
                const float* pa = pbase + ky * 17;
                const float* pb = pa + 17;
                u64 pa2[3], pb2[3];
                #pragma unroll
                for (int kx = 0; kx < 3; kx++) {
                    pa2[kx] = pk2(pa[kx], pa[kx + 1]);
                    pb2[kx] = pk2(pb[kx], pb[kx + 1]);
                }
                const ulonglong2* wp =
                    (const ulonglong2*)&s->w2d[(ic * 9 + ky * 3) * 16 + ocg * 4];
                #pragma unroll
                for (int kx = 0; kx < 3; kx++) {
                    ulonglong2 wA = wp[kx * 8];
                    ulonglong2 wB = wp[kx * 8 + 1];
                    fma2(acc[0][0], wA.x, pa2[kx]); fma2(acc[0][1], wA.x, pb2[kx]);
                    fma2(acc[1][0], wA.y, pa2[kx]); fma2(acc[1][1], wA.y, pb2[kx]);
                    fma2(acc[2][0], wB.x, pa2[kx]); fma2(acc[2][1], wB.x, pb2[kx]);
                    fma2(acc[3][0], wB.y, pa2[kx]); fma2(acc[3][1], wB.y, pb2[kx]);
                }
            }
        }
        #pragma unroll
        for (int k = 0; k < 4; k++) {
            float a0, a1, c0, c1;
            upk2(acc[k][0], a0, a1); upk2(acc[k][1], c0, c1);
            float m = fmaxf(fmaxf(a0, a1), fmaxf(c0, c1)) + s->b2[ocg * 4 + k];
            s->C.p2[(ocg * 4 + k) * 49 + pos] = fmaxf(m, 0.f);
        }
    }
    __syncthreads();

    // ---- Phase 3.5 (p1p dead): weff2/beff fill  +  Phase 4: conv3 -> padded f ----
    // W_eff[oc][ic] = w_a[oc][16+ic] + sum_j w_a[oc][j]*w_q[j][ic]
    for (int o = tid; o < 1024; o += NT) {
        int oc = o >> 5, ic = o & 31;
        float v = __ldg(&gwa[oc * 48 + 16 + ic]);
        #pragma unroll
        for (int j = 0; j < 16; j++)
            v += __ldg(&gwa[oc * 48 + j]) * __ldg(&gwq[j * 32 + ic]);
        s->B.L.weff2[ic * 32 + oc] = make_float2(v, v);
    }
    if (tid < 32) {
        float v = __ldg(&gba[tid]);
        #pragma unroll
        for (int j = 0; j < 16; j++)
            v += __ldg(&gwa[tid * 48 + j]) * __ldg(&gbq[j]);
        s->B.L.beff[tid] = v;
    }
    // conv3 (16->32, 1x1, pad1 -> border=bias), write padded rows of 12
    for (int idx = tid; idx < 3456; idx += NT) {
        int oc = idx / 108, r = idx % 108, y = r / 12, x = r % 12;
        float v = 0.f;
        if (x < 9) {
            v = s->b3[oc];
            if ((unsigned)(y - 1) < 7u && (unsigned)(x - 1) < 7u) {
                const float* pp = &s->C.p2[(y - 1) * 7 + (x - 1)];
                const float* wp = &s->w3[oc * 16];
                #pragma unroll
                for (int ic = 0; ic < 16; ic++) v += wp[ic] * pp[ic * 49];
            }
        }
        s->f[idx] = v;
    }
    __syncthreads();

    // thread roles in depth loop
    const int px4 = lane & 3;        // conf pooled x
    const int yr  = lane >> 2;       // conf conv row 0..7
    const bool aact = lane < 27;     // a-conv active lanes (27 x 4-pos groups)

    // ---- Phase 5: adaptive depth loop ----
    for (int depth = 0; depth < 8; depth++) {
        // --- conf head: relu(conv_cf) -> pool -> dot wcfc -> sigmoid ---
        {
            u64 acc[8];
            #pragma unroll
            for (int k = 0; k < 8; k++)
                acc[k] = *(const u64*)&s->bcf2[wid * 8 + k];
            const int fo = yr * 12 + 2 * px4;
            #pragma unroll 4
            for (int ic = 0; ic < 32; ic++) {
                u64 fv = *(const u64*)&s->f[ic * 108 + fo];
                const ulonglong2* wv = (const ulonglong2*)&s->A.wcf2[ic * 64 + wid * 8];
                ulonglong2 w01 = wv[0], w23 = wv[1], w45 = wv[2], w67 = wv[3];
                fma2(acc[0], w01.x, fv); fma2(acc[1], w01.y, fv);
                fma2(acc[2], w23.x, fv); fma2(acc[3], w23.y, fv);
                fma2(acc[4], w45.x, fv); fma2(acc[5], w45.y, fv);
                fma2(acc[6], w67.x, fv); fma2(acc[7], w67.y, fv);
            }
            float partial = 0.f;
            #pragma unroll
            for (int k = 0; k < 8; k++) {
                float a0, a1;
                upk2(acc[k], a0, a1);
                float m = fmaxf(a0, a1);
                m = fmaxf(m, __shfl_xor_sync(0xffffffffu, m, 4));
                m = fmaxf(m, 0.f);
                if ((yr & 1) == 0)
                    partial += m * s->wcfc[(wid * 8 + k) * 16 + (yr >> 1) * 4 + px4];
            }
            #pragma unroll
            for (int o = 16; o > 0; o >>= 1)
                partial += __shfl_down_sync(0xffffffffu, partial, o);
            if (lane == 0) s->C.R.red[wid] = partial;
        }
        __syncthreads();
        if (tid == 0) {
            float logit = s->bcfc;
            #pragma unroll
            for (int w = 0; w < 8; w++) logit += s->C.R.red[w];
            float confv = 1.f / (1.f + expf(-logit));
            s->C.R.red[32] = (confv < 0.9f) ? 1.f : 0.f;
        }
        __syncthreads();
        if (s->C.R.red[32] == 0.f) break;    // frozen: f never changes again

        // --- fused residual: f += tanh(W_eff @ f + b_eff), tile 4 oc x 4 pos ---
        u64 acc[4][2];
        if (aact) {
            #pragma unroll
            for (int k = 0; k < 4; k++) {
                float bv = s->B.L.beff[wid * 4 + k];
                acc[k][0] = pk2(bv, bv); acc[k][1] = acc[k][0];
            }
            const int fo = lane * 4;
            #pragma unroll 4
            for (int ic = 0; ic < 32; ic++) {
                ulonglong2 fv = *(const ulonglong2*)&s->f[ic * 108 + fo];
                const ulonglong2* wv = (const ulonglong2*)&s->B.L.weff2[ic * 32 + wid * 4];
                ulonglong2 wA = wv[0], wB = wv[1];
                fma2(acc[0][0], wA.x, fv.x); fma2(acc[0][1], wA.x, fv.y);
                fma2(acc[1][0], wA.y, fv.x); fma2(acc[1][1], wA.y, fv.y);
                fma2(acc[2][0], wB.x, fv.x); fma2(acc[2][1], wB.x, fv.y);
                fma2(acc[3][0], wB.y, fv.x); fma2(acc[3][1], wB.y, fv.y);
            }
        }
        __syncthreads();    // all reads of f complete before writes
        if (aact) {
            #pragma unroll
            for (int k = 0; k < 4; k++) {
                float* fp = &s->f[(wid * 4 + k) * 108 + lane * 4];
                float4 fo4 = *(float4*)fp;
                float a0, a1, c0, c1;
                upk2(acc[k][0], a0, a1); upk2(acc[k][1], c0, c1);
                fo4.x += fast_tanh(a0); fo4.y += fast_tanh(a1);
                fo4.z += fast_tanh(c0); fo4.w += fast_tanh(c1);
                *(float4*)fp = fo4;
            }
        }
        __syncthreads();
    }

    // ---- Phase 6: classifier out[10] = w_cls @ f_flat + b_cls ----
    {
        float ac[10];
        #pragma unroll
        for (int o = 0; o < 10; o++) ac[o] = 0.f;
        for (int i = tid; i < 2592; i += NT) {
            int ch = i / 81, r = i - ch * 81;
            int y = r / 9, x = r - 9 * y;
            float fv = s->f[ch * 108 + y * 12 + x];
            #pragma unroll
            for (int o = 0; o < 10; o++)
                ac[o] += __ldg(&gwcls[o * 2592 + i]) * fv;
        }
        #pragma unroll
        for (int o = 0; o < 10; o++) {
            float v = ac[o];
            #pragma unroll
            for (int sh = 16; sh > 0; sh >>= 1)
                v += __shfl_down_sync(0xffffffffu, v, sh);
            if (lane == 0) s->C.R.clsred[wid * 10 + o] = v;
        }
        __syncthreads();
        if (tid < 10) {
            float v = gbcls[tid];
            #pragma unroll
            for (int w = 0; w < 8; w++) v += s->C.R.clsred[w * 10 + tid];
            gout[(size_t)b * 10 + tid] = v;
        }
    }
}

extern "C" void kernel_launch(void* const* d_in, const int* in_sizes, int n_in,
                              void* d_out, int out_size) {
    const float* x     = (const float*)d_in[0];
    const float* w_b1  = (const float*)d_in[1];
    const float* b_b1  = (const float*)d_in[2];
    const float* w_b2  = (const float*)d_in[3];
    const float* b_b2  = (const float*)d_in[4];
    const float* w_b3  = (const float*)d_in[5];
    const float* b_b3  = (const float*)d_in[6];
    const float* w_cf  = (const float*)d_in[7];
    const float* b_cf  = (const float*)d_in[8];
    const float* w_cfc = (const float*)d_in[9];
    const float* b_cfc = (const float*)d_in[10];
    const float* w_q   = (const float*)d_in[11];
    const float* b_q   = (const float*)d_in[12];
    const float* w_a   = (const float*)d_in[13];
    const float* b_a   = (const float*)d_in[14];
    const float* w_cls = (const float*)d_in[15];
    const float* b_cls = (const float*)d_in[16];
    float* out = (float*)d_out;

    int B = in_sizes[0] / (3 * 32 * 32);
    size_t smem = sizeof(Smem);
    cudaFuncSetAttribute(TM_20005957665089_kernel,
                         cudaFuncAttributeMaxDynamicSharedMemorySize, (int)smem);
    TM_20005957665089_kernel<<<B, NT, smem>>>(
        x, w_b1, b_b1, w_b2, b_b2, w_b3, b_b3,
        w_cf, b_cf, w_cfc, b_cfc, w_q, b_q, w_a, b_a,
        w_cls, b_cls, out);
}